// round 3
// baseline (speedup 1.0000x reference)
#include <cuda_runtime.h>
#include <cstdint>

#define NTOK   65536
#define DIMC   256
#define NCODE  1024
#define HWSZ   4096
#define ZSZ    16777216
#define OFF_ZQ      1
#define OFF_PERP    16777217
#define OFF_MINENC  16777218ULL
#define OFF_IDX     83886082ULL

#define SA 260            // A smem row stride (floats): 260 % 32 == 4 -> conflict-free frags
#define SB 68             // B smem row stride (floats)
#define MARGIN 4e-3f
#define NSLOT 4

// smem float offsets
#define F_A     0
#define F_B     33280     // 128*260
#define BCHUNK  8704      // 128*68
#define F_EN    50688     // 33280 + 2*8704
#define F_BEST  51712
#define F_CNT   51840
#define F_CAND  51968
#define SMEM_FLOATS 52992
#define SMEM_BYTES (SMEM_FLOATS * 4)

// ---------------- scratch ----------------
__device__ float  g_et[DIMC * NCODE];
__device__ float  g_en[NCODE];
__device__ float  g_zn[NTOK];
__device__ int    g_idx[NTOK];
__device__ int    g_hist[NCODE];
__device__ double g_loss;

// ---------------- helpers ----------------
__device__ __forceinline__ uint32_t cvt_tf32(float x) {
    uint32_t r;
    asm("cvt.rna.tf32.f32 %0, %1;" : "=r"(r) : "f"(x));
    return r;
}
__device__ __forceinline__ void mma8(float* d, uint32_t a0, uint32_t a1, uint32_t a2,
                                     uint32_t a3, uint32_t b0, uint32_t b1) {
    asm volatile(
        "mma.sync.aligned.m16n8k8.row.col.f32.tf32.tf32.f32 "
        "{%0,%1,%2,%3}, {%4,%5,%6,%7}, {%8,%9}, {%0,%1,%2,%3};"
        : "+f"(d[0]), "+f"(d[1]), "+f"(d[2]), "+f"(d[3])
        : "r"(a0), "r"(a1), "r"(a2), "r"(a3), "r"(b0), "r"(b1));
}
__device__ __forceinline__ unsigned fenc(float f) {
    unsigned u = __float_as_uint(f);
    return (u & 0x80000000u) ? ~u : (u | 0x80000000u);
}
__device__ __forceinline__ float fdec(unsigned e) {
    unsigned u = (e & 0x80000000u) ? (e & 0x7FFFFFFFu) : ~e;
    return __uint_as_float(u);
}

// ---------------- pass1: tf32 mma.sync screen + exact fp32 re-rank ----------------
__global__ void __launch_bounds__(256, 1) k_pass1(const float* __restrict__ z,
                                                  const float* __restrict__ embed) {
    extern __shared__ float sm[];
    float*    As    = sm + F_A;
    float*    Bs    = sm + F_B;
    float*    en    = sm + F_EN;
    unsigned* sbest = (unsigned*)(sm + F_BEST);
    int*      scnt  = (int*)(sm + F_CNT);
    int*      scand = (int*)(sm + F_CAND);

    int tid  = threadIdx.x;
    int warp = tid >> 5;
    int lane = tid & 31;
    int g    = lane >> 2;     // group id (row within frag)
    int tq   = lane & 3;      // thread-in-group (col/k within frag)
    int wm   = warp & 3;      // warp m index (rows wm*32)
    int wn   = warp >> 2;     // warp n index (cols wn*64)
    int n0   = blockIdx.x * 128;
    int b    = n0 >> 12, hw0 = n0 & 4095;

    if (tid < 128) { sbest[tid] = 0xFFFFFFFFu; scnt[tid] = 0; }
    for (int i = tid; i < NCODE; i += 256) en[i] = g_en[i];

    // ---- stage A: 128 tokens x 256 dims fp32 (coalesced over tokens) ----
    {
        int r = tid & 127;
        const float* zb = z + (size_t)b * (DIMC * HWSZ) + hw0 + r;
        float* Ar = As + r * SA;
        int c40 = (tid >> 7) * 32;
#pragma unroll 8
        for (int c4 = c40; c4 < c40 + 32; c4++) {
            float4 v;
            v.x = zb[(size_t)(c4 * 4 + 0) * HWSZ];
            v.y = zb[(size_t)(c4 * 4 + 1) * HWSZ];
            v.z = zb[(size_t)(c4 * 4 + 2) * HWSZ];
            v.w = zb[(size_t)(c4 * 4 + 3) * HWSZ];
            *(float4*)(Ar + c4 * 4) = v;
        }
    }
    // ---- stage B chunk 0 ----
    {
        const float4* src = (const float4*)(embed);
#pragma unroll
        for (int j = 0; j < 8; j++) {
            int idx = tid + j * 256;
            int cl = idx >> 4, k4 = idx & 15;
            float4 v = src[(size_t)cl * 64 + k4];
            uint4 t;
            t.x = cvt_tf32(v.x); t.y = cvt_tf32(v.y);
            t.z = cvt_tf32(v.z); t.w = cvt_tf32(v.w);
            *(uint4*)(Bs + cl * SB + k4 * 4) = t;
        }
    }
    __syncthreads();

    float acc[2][8][4];
#pragma unroll
    for (int mi = 0; mi < 2; mi++)
#pragma unroll
        for (int ni = 0; ni < 8; ni++)
#pragma unroll
            for (int x = 0; x < 4; x++) acc[mi][ni][x] = 0.0f;

    // per-thread candidate state: 4 token rows
    float bv[4]    = {3.4e38f, 3.4e38f, 3.4e38f, 3.4e38f};
    float sd[4][NSLOT];
    int   sc[4][NSLOT];
    int   cntl[4] = {0, 0, 0, 0};
    int   ovf    = 0;

    const float* Arow0 = As + (wm * 32 + g) * SA;

    for (int q = 0; q < 32; q++) {           // q = nt*4 + kc
        int nt = q >> 2, kc = q & 3, par = q & 1;

        // prefetch next B chunk into regs
        float4 rv[8];
        if (q + 1 < 32) {
            int nn = (q + 1) >> 2, nk = (q + 1) & 3;
            const float4* src = (const float4*)(embed + ((size_t)nn * 128) * 256 + nk * 64);
#pragma unroll
            for (int j = 0; j < 8; j++) {
                int idx = tid + j * 256;
                int cl = idx >> 4, k4 = idx & 15;
                rv[j] = src[(size_t)cl * 64 + k4];
            }
        }

        // ---- compute this chunk: 8 k-steps of k8 ----
        const float* Bp = Bs + par * BCHUNK + (wn * 64 + g) * SB;
#pragma unroll
        for (int ks = 0; ks < 8; ks++) {
            int kA = kc * 64 + ks * 8 + tq;
            int kB = ks * 8 + tq;
            uint32_t a[2][4];
#pragma unroll
            for (int mi = 0; mi < 2; mi++) {
                const float* Ar = Arow0 + mi * 16 * SA;
                a[mi][0] = __float_as_uint(Ar[kA]);
                a[mi][1] = __float_as_uint(Ar[8 * SA + kA]);
                a[mi][2] = __float_as_uint(Ar[kA + 4]);
                a[mi][3] = __float_as_uint(Ar[8 * SA + kA + 4]);
            }
            uint32_t bb[8][2];
#pragma unroll
            for (int ni = 0; ni < 8; ni++) {
                const float* Br = Bp + ni * 8 * SB;
                bb[ni][0] = __float_as_uint(Br[kB]);
                bb[ni][1] = __float_as_uint(Br[kB + 4]);
            }
#pragma unroll
            for (int mi = 0; mi < 2; mi++)
#pragma unroll
                for (int ni = 0; ni < 8; ni++)
                    mma8(acc[mi][ni], a[mi][0], a[mi][1], a[mi][2], a[mi][3],
                         bb[ni][0], bb[ni][1]);
        }

        // ---- n-tile epilogue ----
        if (kc == 3) {
#pragma unroll
            for (int mi = 0; mi < 2; mi++) {
#pragma unroll
                for (int ni = 0; ni < 8; ni++) {
                    int code0 = nt * 128 + wn * 64 + ni * 8 + tq * 2;
#pragma unroll
                    for (int x = 0; x < 4; x++) {
                        int ri   = mi * 2 + (x >> 1);        // h = x>>1
                        int code = code0 + (x & 1);
                        float dp = en[code] - 2.0f * acc[mi][ni][x];
                        if (dp < bv[ri] + MARGIN) {
                            if (cntl[ri] == NSLOT) {
                                int m = 0;
                                for (int qq = 0; qq < NSLOT; qq++)
                                    if (sd[ri][qq] < bv[ri] + MARGIN) {
                                        sd[ri][m] = sd[ri][qq];
                                        sc[ri][m] = sc[ri][qq];
                                        m++;
                                    }
                                cntl[ri] = m;
                            }
                            if (cntl[ri] < NSLOT) {
                                sd[ri][cntl[ri]] = dp;
                                sc[ri][cntl[ri]] = code;
                                cntl[ri]++;
                            } else ovf |= (1 << ri);
                            if (dp < bv[ri]) bv[ri] = dp;
                        }
                        acc[mi][ni][x] = 0.0f;
                    }
                }
            }
        }

        // store prefetched chunk to the other buffer
        if (q + 1 < 32) {
            float* Bd = Bs + (1 - par) * BCHUNK;
#pragma unroll
            for (int j = 0; j < 8; j++) {
                int idx = tid + j * 256;
                int cl = idx >> 4, k4 = idx & 15;
                uint4 t;
                t.x = cvt_tf32(rv[j].x); t.y = cvt_tf32(rv[j].y);
                t.z = cvt_tf32(rv[j].z); t.w = cvt_tf32(rv[j].w);
                *(uint4*)(Bd + cl * SB + k4 * 4) = t;
            }
        }
        __syncthreads();
    }

    // ---- merge per-token best across threads ----
#pragma unroll
    for (int ri = 0; ri < 4; ri++) {
        int row = wm * 32 + (ri >> 1) * 16 + (ri & 1) * 8 + g;
        atomicMin(&sbest[row], fenc(bv[ri]));
    }
    __syncthreads();
#pragma unroll
    for (int ri = 0; ri < 4; ri++) {
        int row = wm * 32 + (ri >> 1) * 16 + (ri & 1) * 8 + g;
        if (ovf & (1 << ri)) {
            atomicAdd(&scnt[row], 1000);
        } else {
            float gb = fdec(sbest[row]);
            for (int qq = 0; qq < cntl[ri]; qq++) {
                if (sd[ri][qq] < gb + MARGIN) {
                    int pos = atomicAdd(&scnt[row], 1);
                    if (pos < 8) scand[row * 8 + pos] = sc[ri][qq];
                }
            }
        }
    }
    __syncthreads();

    // ---- exact fp32 re-rank (1 token per thread; A tile exact in smem) ----
    if (tid < 128) {
        int row = tid;
        int cnt = scnt[row];
        float zn = g_zn[n0 + row];
        const float4* ar = (const float4*)(As + row * SA);
        float bestx = 3.4e38f;
        int   besti = 0x7FFFFFFF;
        if (cnt <= 8) {
            for (int qq = 0; qq < cnt; qq++) {
                int code = scand[row * 8 + qq];
                const float4* er = (const float4*)(embed + (size_t)code * 256);
                float dot = 0.0f;
#pragma unroll 8
                for (int c4 = 0; c4 < 64; c4++) {
                    float4 e = er[c4];
                    float4 a = ar[c4];
                    dot = fmaf(a.x, e.x, dot);
                    dot = fmaf(a.y, e.y, dot);
                    dot = fmaf(a.z, e.z, dot);
                    dot = fmaf(a.w, e.w, dot);
                }
                float v = (zn + en[code]) - 2.0f * dot;
                if (v < bestx || (v == bestx && code < besti)) { bestx = v; besti = code; }
            }
        } else {  // overflow fallback: exact full scan
            for (int code = 0; code < NCODE; code++) {
                const float4* er = (const float4*)(embed + (size_t)code * 256);
                float dot = 0.0f;
                for (int c4 = 0; c4 < 64; c4++) {
                    float4 e = er[c4];
                    float4 a = ar[c4];
                    dot = fmaf(a.x, e.x, dot);
                    dot = fmaf(a.y, e.y, dot);
                    dot = fmaf(a.z, e.z, dot);
                    dot = fmaf(a.w, e.w, dot);
                }
                float v = (zn + en[code]) - 2.0f * dot;
                if (v < bestx) { bestx = v; besti = code; }
            }
        }
        g_idx[n0 + row] = besti;
    }
}

// ---------------- |z_n|^2 ----------------
__global__ void k_znorm(const float* __restrict__ z) {
    int b  = blockIdx.x >> 4;
    int hw = ((blockIdx.x & 15) << 8) + threadIdx.x;
    const float* p = z + (size_t)b * DIMC * HWSZ + hw;
    float s = 0.0f;
#pragma unroll 8
    for (int c = 0; c < DIMC; c++) {
        float v = p[(size_t)c * HWSZ];
        s = fmaf(v, v, s);
    }
    g_zn[b * HWSZ + hw] = s;
}

// ---------------- embed transpose + |e_k|^2 + zero accumulators ----------------
__global__ void k_prep(const float* __restrict__ e) {
    int k = blockIdx.x;
    int t = threadIdx.x;
    float4 v = ((const float4*)(e + (size_t)k * DIMC))[t];
    int c = t * 4;
    g_et[(c + 0) * NCODE + k] = v.x;
    g_et[(c + 1) * NCODE + k] = v.y;
    g_et[(c + 2) * NCODE + k] = v.z;
    g_et[(c + 3) * NCODE + k] = v.w;
    float s = v.x * v.x + v.y * v.y + v.z * v.z + v.w * v.w;
#pragma unroll
    for (int o = 16; o; o >>= 1) s += __shfl_down_sync(0xffffffffu, s, o);
    __shared__ float sh[2];
    if ((t & 31) == 0) sh[t >> 5] = s;
    __syncthreads();
    if (t == 0) {
        g_en[k]   = sh[0] + sh[1];
        g_hist[k] = 0;
        if (k == 0) g_loss = 0.0;
    }
}

// ---------------- z_q gather + loss ----------------
__global__ void k_epi(const float* __restrict__ z, float* __restrict__ out) {
    size_t i = (size_t)blockIdx.x * 256 + threadIdx.x;
    int hw = (int)(i & 4095);
    int c  = (int)((i >> 12) & 255);
    int b  = (int)(i >> 20);
    int k  = g_idx[b * HWSZ + hw];
    float zv = z[i];
    float q  = __ldg(&g_et[(size_t)c * NCODE + k]);
    float d  = q - zv;
    out[OFF_ZQ + i] = zv + d;
    float s = d * d;
#pragma unroll
    for (int o = 16; o; o >>= 1) s += __shfl_down_sync(0xffffffffu, s, o);
    __shared__ float red[8];
    int t = threadIdx.x;
    if ((t & 31) == 0) red[t >> 5] = s;
    __syncthreads();
    if (t < 8) {
        float w = red[t];
#pragma unroll
        for (int o = 4; o; o >>= 1) w += __shfl_down_sync(0x000000ffu, w, o);
        if (t == 0) atomicAdd(&g_loss, (double)w);
    }
}

// ---------------- one-hot scatter + idx + histogram ----------------
__global__ void k_scat(float* __restrict__ out) {
    int n = blockIdx.x * 256 + threadIdx.x;
    int k = g_idx[n];
    out[OFF_MINENC + (size_t)n * NCODE + k] = 1.0f;
    out[OFF_IDX + n] = (float)k;
    atomicAdd(&g_hist[k], 1);
}

// ---------------- finalize ----------------
__global__ void k_fin(float* __restrict__ out) {
    int t = threadIdx.x;
    float em = (float)g_hist[t] * (1.0f / 65536.0f);
    float v = em * logf(em + 1e-10f);
    __shared__ float sh[32];
#pragma unroll
    for (int o = 16; o; o >>= 1) v += __shfl_down_sync(0xffffffffu, v, o);
    if ((t & 31) == 0) sh[t >> 5] = v;
    __syncthreads();
    if (t < 32) {
        float w = sh[t];
#pragma unroll
        for (int o = 16; o; o >>= 1) w += __shfl_down_sync(0xffffffffu, w, o);
        if (t == 0) {
            out[OFF_PERP] = expf(-w);
            out[0] = (float)(g_loss * (1.25 / 16777216.0));
        }
    }
}

// ---------------- launch ----------------
extern "C" void kernel_launch(void* const* d_in, const int* in_sizes, int n_in,
                              void* d_out, int out_size) {
    const float* z = (const float*)d_in[0];
    const float* e = (const float*)d_in[1];
    float* out = (float*)d_out;
    (void)in_sizes; (void)n_in; (void)out_size;

    static int attr_set = 0;
    if (!attr_set) {
        cudaFuncSetAttribute(k_pass1, cudaFuncAttributeMaxDynamicSharedMemorySize, SMEM_BYTES);
        attr_set = 1;
    }

    k_prep  <<<NCODE, 64>>>(e);
    k_znorm <<<256, 256>>>(z);
    cudaMemsetAsync(out + OFF_MINENC, 0, 268435456ULL);
    k_pass1 <<<NTOK / 128, 256, SMEM_BYTES>>>(z, e);
    k_epi   <<<ZSZ / 256, 256>>>(z, out);
    k_scat  <<<NTOK / 256, 256>>>(out);
    k_fin   <<<1, 1024>>>(out);
}